// round 2
// baseline (speedup 1.0000x reference)
#include <cuda_runtime.h>
#include <math.h>

#define CNT 262144.0f

__device__ float g_xperm[4*1024*64*64];
__device__ float g_wy[4*64*65536];
__device__ float g_Gx[4*64*64];
__device__ float g_sx[4*64];
__device__ float g_RT[4*64*64];
__device__ float g_beta[4*64];
__device__ float g_WcT[64*64];
__device__ float g_Sw[64];
__device__ float g_sum[64], g_sumsq[64];
__device__ float g_scale[64], g_shift[64];

__global__ void k0() {
    int i = blockIdx.x * 256 + threadIdx.x;
    if (i < 16384) g_Gx[i] = 0.f;
    if (i < 256) g_sx[i] = 0.f;
    if (i < 64) { g_sum[i] = 0.f; g_sumsq[i] = 0.f; }
}

// transpose x -> x_perm[b][j][cp][e], Gram(x), column sums
__global__ __launch_bounds__(256) void k1(const float* __restrict__ x) {
    __shared__ float st[128 * 64];
    const int b = blockIdx.y, t = threadIdx.x;
    const int e_ld = t >> 2, q = t & 3;
    const int g = t >> 6, tt = t & 63;
    const int gi = (tt >> 3) * 8, gj = (tt & 7) * 8;
    float gacc[8][8];
#pragma unroll
    for (int r = 0; r < 8; r++)
#pragma unroll
        for (int c = 0; c < 8; c++) gacc[r][c] = 0.f;
    float sxacc = 0.f;

    for (int tile = blockIdx.x; tile < 512; tile += 128) {
        const int n0 = tile * 128;
        const float* xrow = x + ((long)(b * 64 + e_ld)) * 65536 + n0 + q * 32;
#pragma unroll
        for (int k = 0; k < 8; k++) {
            float4 v = *(const float4*)(xrow + 4 * k);
            int s = q * 32 + 4 * k;
            st[(s + 0) * 64 + e_ld] = v.x;
            st[(s + 1) * 64 + e_ld] = v.y;
            st[(s + 2) * 64 + e_ld] = v.z;
            st[(s + 3) * 64 + e_ld] = v.w;
            sxacc += v.x + v.y + v.z + v.w;
        }
        __syncthreads();
        { // write x_perm rows
            const int s = t >> 1, h = t & 1;
            const int n = n0 + s, j = n & 1023, cp = n >> 10;
            float4* dst = (float4*)(g_xperm + (((long)b * 1024 + j) * 64 + cp) * 64 + h * 32);
            const float4* src = (const float4*)(st + s * 64 + h * 32);
#pragma unroll
            for (int k = 0; k < 8; k++) dst[k] = src[k];
        }
        for (int it = 0; it < 32; it++) {
            const int s = g + it * 4;
            float4 a0 = *(const float4*)(st + s * 64 + gi);
            float4 a1 = *(const float4*)(st + s * 64 + gi + 4);
            float4 b0 = *(const float4*)(st + s * 64 + gj);
            float4 b1 = *(const float4*)(st + s * 64 + gj + 4);
            float av[8] = {a0.x,a0.y,a0.z,a0.w,a1.x,a1.y,a1.z,a1.w};
            float bv[8] = {b0.x,b0.y,b0.z,b0.w,b1.x,b1.y,b1.z,b1.w};
#pragma unroll
            for (int r = 0; r < 8; r++)
#pragma unroll
                for (int c = 0; c < 8; c++) gacc[r][c] += av[r] * bv[c];
        }
        __syncthreads();
    }
    for (int idx = t; idx < 4096; idx += 256) st[idx] = 0.f;
    __syncthreads();
#pragma unroll
    for (int r = 0; r < 8; r++)
#pragma unroll
        for (int c = 0; c < 8; c++) atomicAdd(&st[(gi + r) * 64 + gj + c], gacc[r][c]);
    __syncthreads();
    float* Gb = g_Gx + b * 4096;
    for (int idx = t; idx < 4096; idx += 256) atomicAdd(&Gb[idx], st[idx]);
    sxacc += __shfl_down_sync(0xffffffffu, sxacc, 1);
    sxacc += __shfl_down_sync(0xffffffffu, sxacc, 2);
    if (q == 0) atomicAdd(&g_sx[b * 64 + e_ld], sxacc);
}

// f = Pw G Tw^T + rank1, softmax, R^T, beta, WcT, Sw
__global__ __launch_bounds__(256) void k2(
    const float* __restrict__ tw, const float* __restrict__ tb,
    const float* __restrict__ pw, const float* __restrict__ pb,
    const float* __restrict__ gw, const float* __restrict__ gb,
    const float* __restrict__ ww) {
    __shared__ float A[64 * 68], Bf[64 * 68];
    __shared__ float s_sx[64], s_tsx[64], s_psx[64], s_tb[64], s_pb[64], s_gb[64];
    const int b = blockIdx.x, t = threadIdx.x;
    const int ty = t >> 4, tx = t & 15;
    if (t < 64) { s_sx[t] = g_sx[b*64+t]; s_tb[t] = tb[t]; s_pb[t] = pb[t]; s_gb[t] = gb[t]; }
    __syncthreads();
    if (t < 64) {
        float a1 = 0.f, a2 = 0.f;
        for (int e = 0; e < 64; e++) { a1 += tw[t*64+e]*s_sx[e]; a2 += pw[t*64+e]*s_sx[e]; }
        s_tsx[t] = a1; s_psx[t] = a2;
    }
    for (int idx = t; idx < 4096; idx += 256) A[(idx & 63) * 68 + (idx >> 6)] = tw[idx];
    __syncthreads();
    const float* Gb = g_Gx + b * 4096;
    float acc[4][4];
#pragma unroll
    for (int i = 0; i < 4; i++)
#pragma unroll
        for (int j = 0; j < 4; j++) acc[i][j] = 0.f;
    for (int ep = 0; ep < 64; ep++) {
        float4 av = *(const float4*)(Gb + ep*64 + 4*ty);
        float4 bv = *(const float4*)(A + ep*68 + 4*tx);
        float aa[4]={av.x,av.y,av.z,av.w}, bb[4]={bv.x,bv.y,bv.z,bv.w};
#pragma unroll
        for (int i = 0; i < 4; i++)
#pragma unroll
            for (int j = 0; j < 4; j++) acc[i][j] += aa[i]*bb[j];
    }
    __syncthreads();
#pragma unroll
    for (int i = 0; i < 4; i++)
#pragma unroll
        for (int j = 0; j < 4; j++) Bf[(4*ty+i)*68 + 4*tx+j] = acc[i][j];
    for (int idx = t; idx < 4096; idx += 256) A[(idx & 63) * 68 + (idx >> 6)] = pw[idx];
    __syncthreads();
#pragma unroll
    for (int i = 0; i < 4; i++)
#pragma unroll
        for (int j = 0; j < 4; j++) acc[i][j] = 0.f;
    for (int e = 0; e < 64; e++) {
        float4 av = *(const float4*)(A + e*68 + 4*ty);
        float4 bv = *(const float4*)(Bf + e*68 + 4*tx);
        float aa[4]={av.x,av.y,av.z,av.w}, bb[4]={bv.x,bv.y,bv.z,bv.w};
#pragma unroll
        for (int i = 0; i < 4; i++)
#pragma unroll
            for (int j = 0; j < 4; j++) acc[i][j] += aa[i]*bb[j];
    }
    __syncthreads();
#pragma unroll
    for (int i = 0; i < 4; i++)
#pragma unroll
        for (int j = 0; j < 4; j++) {
            int c = 4*ty+i, d = 4*tx+j;
            Bf[c*68+d] = acc[i][j] + s_pb[c]*(s_tsx[d] + 65536.f*s_tb[d]) + s_psx[c]*s_tb[d];
        }
    __syncthreads();
    { // softmax rows (over d), write attn^T into A[d][c]
        const int w = t >> 5, lane = t & 31;
        for (int c = w*8; c < w*8+8; c++) {
            float v0 = Bf[c*68+lane], v1 = Bf[c*68+32+lane];
            float m = fmaxf(v0, v1);
#pragma unroll
            for (int o = 16; o >= 1; o >>= 1) m = fmaxf(m, __shfl_xor_sync(0xffffffffu, m, o));
            float e0 = expf(v0-m), e1 = expf(v1-m), s = e0+e1;
#pragma unroll
            for (int o = 16; o >= 1; o >>= 1) s += __shfl_xor_sync(0xffffffffu, s, o);
            float inv = 1.f/s;
            A[lane*68+c] = e0*inv;
            A[(lane+32)*68+c] = e1*inv;
        }
    }
    __syncthreads();
    if (t < 64) {
        float bs = 0.f;
        for (int d = 0; d < 64; d++) bs += A[d*68+t]*s_gb[d];
        g_beta[b*64+t] = bs;
    }
#pragma unroll
    for (int i = 0; i < 4; i++)
#pragma unroll
        for (int j = 0; j < 4; j++) acc[i][j] = 0.f;
    for (int d = 0; d < 64; d++) {
        float4 av = *(const float4*)(gw + d*64 + 4*ty);
        float4 bv = *(const float4*)(A + d*68 + 4*tx);
        float aa[4]={av.x,av.y,av.z,av.w}, bb[4]={bv.x,bv.y,bv.z,bv.w};
#pragma unroll
        for (int i = 0; i < 4; i++)
#pragma unroll
            for (int j = 0; j < 4; j++) acc[i][j] += aa[i]*bb[j];
    }
#pragma unroll
    for (int i = 0; i < 4; i++)
        *(float4*)(g_RT + b*4096 + (4*ty+i)*64 + 4*tx) = make_float4(acc[i][0],acc[i][1],acc[i][2],acc[i][3]);
    if (b == 0) {
        for (int idx = t; idx < 4096; idx += 256) g_WcT[(idx & 63)*64 + (idx >> 6)] = ww[idx];
        if (t < 64) {
            float s = 0.f;
            for (int cp = 0; cp < 64; cp++) s += ww[t*64+cp];
            g_Sw[t] = s;
        }
    }
}

// per (b,j): P = Wc X; Wy = P R^T + bias; store + BN stats
__global__ __launch_bounds__(256) void k3(const float* __restrict__ wb) {
    __shared__ float sXP[64*64], sR[64*64];
    const int b = blockIdx.y, jb = blockIdx.x, t = threadIdx.x;
    const int ty = t >> 4, tx = t & 15;
    {
        const float4* sx_ = (const float4*)(g_xperm + (((long)b*1024 + jb) * 64) * 64);
        const float4* sr_ = (const float4*)(g_RT + b*4096);
        float4 *dx = (float4*)sXP, *dr = (float4*)sR;
#pragma unroll
        for (int k = 0; k < 4; k++) { dx[t+256*k] = sx_[t+256*k]; dr[t+256*k] = sr_[t+256*k]; }
    }
    __syncthreads();
    float acc[4][4];
#pragma unroll
    for (int i = 0; i < 4; i++)
#pragma unroll
        for (int j = 0; j < 4; j++) acc[i][j] = 0.f;
    for (int cp = 0; cp < 64; cp++) {  // Pm[e][oc] = sum_cp X[cp][e]*WcT[cp][oc]
        float4 av = *(const float4*)(sXP + cp*64 + 4*ty);
        float4 bv = __ldg((const float4*)(g_WcT + cp*64 + 4*tx));
        float aa[4]={av.x,av.y,av.z,av.w}, bb[4]={bv.x,bv.y,bv.z,bv.w};
#pragma unroll
        for (int i = 0; i < 4; i++)
#pragma unroll
            for (int j = 0; j < 4; j++) acc[i][j] += aa[i]*bb[j];
    }
    __syncthreads();
#pragma unroll
    for (int i = 0; i < 4; i++)
#pragma unroll
        for (int j = 0; j < 4; j++) sXP[(4*ty+i)*64 + 4*tx+j] = acc[i][j];
    __syncthreads();
#pragma unroll
    for (int i = 0; i < 4; i++)
#pragma unroll
        for (int j = 0; j < 4; j++) acc[i][j] = 0.f;
    for (int e = 0; e < 64; e++) {  // Wy[oc][c] = sum_e Pm[e][oc]*Rt[e][c]
        float4 av = *(const float4*)(sXP + e*64 + 4*ty);
        float4 bv = *(const float4*)(sR + e*64 + 4*tx);
        float aa[4]={av.x,av.y,av.z,av.w}, bb[4]={bv.x,bv.y,bv.z,bv.w};
#pragma unroll
        for (int i = 0; i < 4; i++)
#pragma unroll
            for (int j = 0; j < 4; j++) acc[i][j] += aa[i]*bb[j];
    }
    float4 bet = __ldg((const float4*)(g_beta + b*64 + 4*tx));
    float be[4] = {bet.x, bet.y, bet.z, bet.w};
    float ps[4], pq[4];
#pragma unroll
    for (int i = 0; i < 4; i++) {
        int oc = 4*ty+i;
        float sw = __ldg(&g_Sw[oc]), wbi = __ldg(&wb[oc]);
        float s = 0.f, q = 0.f;
#pragma unroll
        for (int j = 0; j < 4; j++) {
            float v = acc[i][j] + be[j]*sw + wbi;
            acc[i][j] = v; s += v; q += v*v;
        }
        ps[i] = s; pq[i] = q;
        *(float4*)(g_wy + ((long)(b*64+oc))*65536 + jb*64 + 4*tx) =
            make_float4(acc[i][0],acc[i][1],acc[i][2],acc[i][3]);
    }
#pragma unroll
    for (int o = 8; o >= 1; o >>= 1)
#pragma unroll
        for (int i = 0; i < 4; i++) {
            ps[i] += __shfl_xor_sync(0xffffffffu, ps[i], o);
            pq[i] += __shfl_xor_sync(0xffffffffu, pq[i], o);
        }
    if (tx == 0)
#pragma unroll
        for (int i = 0; i < 4; i++) {
            atomicAdd(&g_sum[4*ty+i], ps[i]);
            atomicAdd(&g_sumsq[4*ty+i], pq[i]);
        }
}

__global__ void k4(const float* __restrict__ gamma, const float* __restrict__ bnb) {
    int t = threadIdx.x;
    if (t < 64) {
        float m = g_sum[t] / CNT;
        float v = g_sumsq[t] / CNT - m*m;
        float sc = gamma[t] * rsqrtf(v + 1e-5f);
        g_scale[t] = sc;
        g_shift[t] = bnb[t] - m*sc;
    }
}

__global__ __launch_bounds__(256) void k5(const float* __restrict__ x, float* __restrict__ out) {
    long i4 = (long)blockIdx.x * 256 + threadIdx.x;
    int ch = (int)(i4 >> 14) & 63;
    float sc = __ldg(&g_scale[ch]), sh = __ldg(&g_shift[ch]);
    float4 w = ((const float4*)g_wy)[i4];
    float4 xv = ((const float4*)x)[i4];
    float4 o;
    o.x = w.x*sc + sh + xv.x;
    o.y = w.y*sc + sh + xv.y;
    o.z = w.z*sc + sh + xv.z;
    o.w = w.w*sc + sh + xv.w;
    ((float4*)out)[i4] = o;
}

extern "C" void kernel_launch(void* const* d_in, const int* in_sizes, int n_in,
                              void* d_out, int out_size) {
    const float* x  = (const float*)d_in[0];
    const float* tw = (const float*)d_in[1];
    const float* tb = (const float*)d_in[2];
    const float* pw = (const float*)d_in[3];
    const float* pb = (const float*)d_in[4];
    const float* gw = (const float*)d_in[5];
    const float* gb = (const float*)d_in[6];
    const float* ww = (const float*)d_in[7];
    const float* wb = (const float*)d_in[8];
    const float* gamma = (const float*)d_in[9];
    const float* bnb = (const float*)d_in[10];
    float* out = (float*)d_out;
    k0<<<64, 256>>>();
    k1<<<dim3(128, 4), 256>>>(x);
    k2<<<4, 256>>>(tw, tb, pw, pb, gw, gb, ww);
    k3<<<dim3(1024, 4), 256>>>(wb);
    k4<<<1, 64>>>(gamma, bnb);
    k5<<<16384, 256>>>(x, out);
}

// round 4
// speedup vs baseline: 1.8651x; 1.8651x over previous
#include <cuda_runtime.h>
#include <math.h>

#define CNT 262144.0f

__device__ float g_T[4L*64*65536];   // [b][oc][e*1024+j]
__device__ float g_Gx[4*64*64];
__device__ float g_Gq[4*64*64];
__device__ float g_sx[4*64];
__device__ float g_R[4*64*64];       // R[c][e]
__device__ float g_beta[4*64];
__device__ float g_Sw[64];
__device__ float g_sum[64], g_sumsq[64];
__device__ float g_scale[64], g_shift[64];

__device__ __forceinline__ unsigned f2tf(float f) {
    unsigned u; asm("cvt.rna.tf32.f32 %0, %1;" : "=r"(u) : "f"(f)); return u;
}
__device__ __forceinline__ void mma8(float* c, const unsigned* a, const unsigned* b) {
    asm("mma.sync.aligned.m16n8k8.row.col.f32.tf32.tf32.f32 "
        "{%0,%1,%2,%3},{%4,%5,%6,%7},{%8,%9},{%0,%1,%2,%3};"
        : "+f"(c[0]), "+f"(c[1]), "+f"(c[2]), "+f"(c[3])
        : "r"(a[0]), "r"(a[1]), "r"(a[2]), "r"(a[3]), "r"(b[0]), "r"(b[1]));
}

__global__ void k0() {
    int i = blockIdx.x * 256 + threadIdx.x;
    if (i < 16384) { g_Gx[i] = 0.f; g_Gq[i] = 0.f; }
    if (i < 256) g_sx[i] = 0.f;
    if (i < 64) { g_sum[i] = 0.f; g_sumsq[i] = 0.f; }
}

// Gram: Gx = Xhi Xhi^T, Gq = Xhi Xlo^T; plus column sums.
__global__ __launch_bounds__(256) void kG(const float* __restrict__ x) {
    __shared__ __align__(16) float Xs[64 * 132];
    const int b = blockIdx.y, t = threadIdx.x, w = t >> 5, lane = t & 31;
    const int gid = lane >> 2, tig = lane & 3;
    const int rs = w & 3, cg = w >> 2;
    const int cp = t >> 2, q = t & 3;
    float P[4][4], Q[4][4];
#pragma unroll
    for (int u = 0; u < 4; u++)
#pragma unroll
        for (int i = 0; i < 4; i++) { P[u][i] = 0.f; Q[u][i] = 0.f; }
    float sx = 0.f;
    for (int tt = 0; tt < 4; tt++) {
        int n0 = (blockIdx.x * 4 + tt) * 128;
        const float* src = x + ((long)(b * 64 + cp)) * 65536 + n0 + q * 32;
#pragma unroll
        for (int k = 0; k < 8; k++) {
            float4 v = *(const float4*)(src + 4 * k);
            sx += v.x + v.y + v.z + v.w;
            *(float4*)(Xs + cp * 132 + q * 32 + 4 * k) = v;
        }
        __syncthreads();
        for (int ks = 0; ks < 16; ks++) {
            const int col = 8 * ks + tig, e0 = rs * 16 + gid;
            unsigned ah[4];
            ah[0] = f2tf(Xs[e0 * 132 + col]);
            ah[1] = f2tf(Xs[(e0 + 8) * 132 + col]);
            ah[2] = f2tf(Xs[e0 * 132 + col + 4]);
            ah[3] = f2tf(Xs[(e0 + 8) * 132 + col + 4]);
#pragma unroll
            for (int u = 0; u < 4; u++) {
                int ep = cg * 32 + 8 * u + gid;
                float f0 = Xs[ep * 132 + col], f1 = Xs[ep * 132 + col + 4];
                unsigned bh[2] = {f2tf(f0), f2tf(f1)};
                unsigned bl[2] = {f2tf(f0 - __uint_as_float(bh[0])),
                                  f2tf(f1 - __uint_as_float(bh[1]))};
                mma8(P[u], ah, bh);
                mma8(Q[u], ah, bl);
            }
        }
        __syncthreads();
    }
    float* Gp = g_Gx + b * 4096;
    float* Gq = g_Gq + b * 4096;
#pragma unroll
    for (int u = 0; u < 4; u++) {
        int r0 = rs * 16 + gid, c0 = cg * 32 + 8 * u + 2 * tig;
        atomicAdd(&Gp[r0 * 64 + c0], P[u][0]);
        atomicAdd(&Gp[r0 * 64 + c0 + 1], P[u][1]);
        atomicAdd(&Gp[(r0 + 8) * 64 + c0], P[u][2]);
        atomicAdd(&Gp[(r0 + 8) * 64 + c0 + 1], P[u][3]);
        atomicAdd(&Gq[r0 * 64 + c0], Q[u][0]);
        atomicAdd(&Gq[r0 * 64 + c0 + 1], Q[u][1]);
        atomicAdd(&Gq[(r0 + 8) * 64 + c0], Q[u][2]);
        atomicAdd(&Gq[(r0 + 8) * 64 + c0 + 1], Q[u][3]);
    }
    sx += __shfl_down_sync(0xffffffffu, sx, 1);
    sx += __shfl_down_sync(0xffffffffu, sx, 2);
    if (q == 0) atomicAdd(&g_sx[b * 64 + cp], sx);
}

// T[b][oc][e*1024+j] = sum_ch Wc[oc][ch] * x[b][e][ch*1024+j]
// block: (jhalf, b*64+e). X_e[ch][j] rows are contiguous 1024-float chunks.
__global__ __launch_bounds__(256) void kT(const float* __restrict__ x,
                                          const float* __restrict__ ww) {
    __shared__ __align__(16) float Xs[64 * 132];
    const int be = blockIdx.y;              // b*64 + e
    const int b = be >> 6, e = be & 63;
    const int t = threadIdx.x, w = t >> 5, lane = t & 31;
    const int gid = lane >> 2, tig = lane & 3;
    const int rs = w & 3, jh = w >> 2;
    const int ch_ld = t >> 2, q = t & 3;
    unsigned aw[8][4];
#pragma unroll
    for (int k = 0; k < 8; k++) {
        int r = rs * 16 + gid, c = 8 * k + tig;
        aw[k][0] = f2tf(ww[r * 64 + c]);
        aw[k][1] = f2tf(ww[(r + 8) * 64 + c]);
        aw[k][2] = f2tf(ww[r * 64 + c + 4]);
        aw[k][3] = f2tf(ww[(r + 8) * 64 + c + 4]);
    }
    const float* xe = x + (long)be * 65536;
    for (int tt = 0; tt < 4; tt++) {
        int j0 = blockIdx.x * 512 + tt * 128;
        const float* src = xe + ch_ld * 1024 + j0 + q * 32;
#pragma unroll
        for (int k = 0; k < 8; k++)
            *(float4*)(Xs + ch_ld * 132 + q * 32 + 4 * k) = *(const float4*)(src + 4 * k);
        __syncthreads();
#pragma unroll
        for (int half = 0; half < 2; half++) {
            float acc[4][4];
#pragma unroll
            for (int u = 0; u < 4; u++)
#pragma unroll
                for (int i = 0; i < 4; i++) acc[u][i] = 0.f;
            int nb = jh * 64 + half * 32;
#pragma unroll
            for (int k = 0; k < 8; k++) {
#pragma unroll
                for (int u = 0; u < 4; u++) {
                    int nn = nb + 8 * u + gid;
                    unsigned bh[2] = {f2tf(Xs[(8 * k + tig) * 132 + nn]),
                                      f2tf(Xs[(8 * k + tig + 4) * 132 + nn])};
                    mma8(acc[u], aw[k], bh);
                }
            }
#pragma unroll
            for (int u = 0; u < 4; u++) {
                int oc = rs * 16 + gid, nn = nb + 8 * u + 2 * tig;
                float* d0 = g_T + ((long)(b * 64 + oc)) * 65536 + e * 1024 + j0 + nn;
                *(float2*)d0 = make_float2(acc[u][0], acc[u][1]);
                *(float2*)(d0 + 8L * 65536) = make_float2(acc[u][2], acc[u][3]);
            }
        }
        __syncthreads();
    }
}

// f = Pw G Tw^T + rank1, softmax, R, beta, Sw  (G = Gx + Gq + Gq^T)
__global__ __launch_bounds__(256) void k2(
    const float* __restrict__ tw, const float* __restrict__ tb,
    const float* __restrict__ pw, const float* __restrict__ pb,
    const float* __restrict__ gw, const float* __restrict__ gb,
    const float* __restrict__ ww) {
    __shared__ float A[64 * 68], Bf[64 * 68];
    __shared__ float s_sx[64], s_tsx[64], s_psx[64], s_tb[64], s_pb[64], s_gb[64];
    const int b = blockIdx.x, t = threadIdx.x;
    const int ty = t >> 4, tx = t & 15;
    if (t < 64) { s_sx[t] = g_sx[b*64+t]; s_tb[t] = tb[t]; s_pb[t] = pb[t]; s_gb[t] = gb[t]; }
    __syncthreads();
    if (t < 64) {
        float a1 = 0.f, a2 = 0.f;
        for (int e = 0; e < 64; e++) { a1 += tw[t*64+e]*s_sx[e]; a2 += pw[t*64+e]*s_sx[e]; }
        s_tsx[t] = a1; s_psx[t] = a2;
    }
    for (int idx = t; idx < 4096; idx += 256) A[(idx & 63) * 68 + (idx >> 6)] = tw[idx];
    __syncthreads();
    const float* Gx = g_Gx + b * 4096;
    const float* Gq = g_Gq + b * 4096;
    float acc[4][4];
#pragma unroll
    for (int i = 0; i < 4; i++)
#pragma unroll
        for (int j = 0; j < 4; j++) acc[i][j] = 0.f;
    for (int ep = 0; ep < 64; ep++) {
        float4 g1 = *(const float4*)(Gx + ep*64 + 4*ty);
        float4 g2 = *(const float4*)(Gq + ep*64 + 4*ty);
        float aa[4];
        aa[0] = g1.x + g2.x + Gq[(4*ty+0)*64 + ep];
        aa[1] = g1.y + g2.y + Gq[(4*ty+1)*64 + ep];
        aa[2] = g1.z + g2.z + Gq[(4*ty+2)*64 + ep];
        aa[3] = g1.w + g2.w + Gq[(4*ty+3)*64 + ep];
        float4 bv = *(const float4*)(A + ep*68 + 4*tx);
        float bb[4] = {bv.x, bv.y, bv.z, bv.w};
#pragma unroll
        for (int i = 0; i < 4; i++)
#pragma unroll
            for (int j = 0; j < 4; j++) acc[i][j] += aa[i]*bb[j];
    }
    __syncthreads();
#pragma unroll
    for (int i = 0; i < 4; i++)
#pragma unroll
        for (int j = 0; j < 4; j++) Bf[(4*ty+i)*68 + 4*tx+j] = acc[i][j];
    for (int idx = t; idx < 4096; idx += 256) A[(idx & 63) * 68 + (idx >> 6)] = pw[idx];
    __syncthreads();
#pragma unroll
    for (int i = 0; i < 4; i++)
#pragma unroll
        for (int j = 0; j < 4; j++) acc[i][j] = 0.f;
    for (int e = 0; e < 64; e++) {
        float4 av = *(const float4*)(A + e*68 + 4*ty);
        float4 bv = *(const float4*)(Bf + e*68 + 4*tx);
        float aa[4]={av.x,av.y,av.z,av.w}, bb[4]={bv.x,bv.y,bv.z,bv.w};
#pragma unroll
        for (int i = 0; i < 4; i++)
#pragma unroll
            for (int j = 0; j < 4; j++) acc[i][j] += aa[i]*bb[j];
    }
    __syncthreads();
#pragma unroll
    for (int i = 0; i < 4; i++)
#pragma unroll
        for (int j = 0; j < 4; j++) {
            int c = 4*ty+i, d = 4*tx+j;
            Bf[c*68+d] = acc[i][j] + s_pb[c]*(s_tsx[d] + 65536.f*s_tb[d]) + s_psx[c]*s_tb[d];
        }
    __syncthreads();
    {
        const int w = t >> 5, lane = t & 31;
        for (int c = w*8; c < w*8+8; c++) {
            float v0 = Bf[c*68+lane], v1 = Bf[c*68+32+lane];
            float m = fmaxf(v0, v1);
#pragma unroll
            for (int o = 16; o >= 1; o >>= 1) m = fmaxf(m, __shfl_xor_sync(0xffffffffu, m, o));
            float e0 = expf(v0-m), e1 = expf(v1-m), s = e0+e1;
#pragma unroll
            for (int o = 16; o >= 1; o >>= 1) s += __shfl_xor_sync(0xffffffffu, s, o);
            float inv = 1.f/s;
            A[lane*68+c] = e0*inv;
            A[(lane+32)*68+c] = e1*inv;
        }
    }
    __syncthreads();
    if (t < 64) {
        float bs = 0.f;
        for (int d = 0; d < 64; d++) bs += A[d*68+t]*s_gb[d];
        g_beta[b*64+t] = bs;
    }
#pragma unroll
    for (int i = 0; i < 4; i++)
#pragma unroll
        for (int j = 0; j < 4; j++) acc[i][j] = 0.f;
    for (int d = 0; d < 64; d++) {
        float4 av = *(const float4*)(gw + d*64 + 4*ty);
        float4 bv = *(const float4*)(A + d*68 + 4*tx);
        float aa[4]={av.x,av.y,av.z,av.w}, bb[4]={bv.x,bv.y,bv.z,bv.w};
#pragma unroll
        for (int i = 0; i < 4; i++)
#pragma unroll
            for (int j = 0; j < 4; j++) acc[i][j] += aa[i]*bb[j];
    }
    // acc[i][j] = R[c=4tx+j][e=4ty+i]; store row-major R[c][e]
#pragma unroll
    for (int i = 0; i < 4; i++)
#pragma unroll
        for (int j = 0; j < 4; j++)
            g_R[b*4096 + (4*tx+j)*64 + (4*ty+i)] = acc[i][j];
    if (b == 0 && t < 64) {
        float s = 0.f;
        for (int cp = 0; cp < 64; cp++) s += ww[t*64+cp];
        g_Sw[t] = s;
    }
}

// wy[b][oc][j*64+c] = sum_e R[c][e]*T[b][oc][e*1024+j] + beta[c]*Sw[oc] + wb[oc]
__global__ __launch_bounds__(256) void kB(const float* __restrict__ wbias,
                                          float* __restrict__ out) {
    __shared__ __align__(16) float As[64 * 72];
    __shared__ __align__(16) float Ds[64 * 68];
    __shared__ float sb[64];
    const int oc = blockIdx.x, b = blockIdx.y, t = threadIdx.x;
    const int w = t >> 5, lane = t & 31, gid = lane >> 2, tig = lane & 3;
    const int cs = w & 3, jh = w >> 2;
    if (t < 64) sb[t] = g_beta[b * 64 + t];
    const float swv = g_Sw[oc], wbv = wbias[oc];
    unsigned ar[8][4];
    const float* Rb = g_R + b * 4096;
#pragma unroll
    for (int k = 0; k < 8; k++) {
        int r = cs * 16 + gid, c = 8 * k + tig;
        ar[k][0] = f2tf(Rb[r * 64 + c]);
        ar[k][1] = f2tf(Rb[(r + 8) * 64 + c]);
        ar[k][2] = f2tf(Rb[r * 64 + c + 4]);
        ar[k][3] = f2tf(Rb[(r + 8) * 64 + c + 4]);
    }
    const float* Tb = g_T + ((long)(b * 64 + oc)) * 65536;
    float* ob = out + ((long)(b * 64 + oc)) * 65536;
    float ls = 0.f, lq = 0.f;
    const int e = t >> 2, q4 = t & 3;
    __syncthreads();
    for (int jt = 0; jt < 16; jt++) {
        int j0 = jt * 64;
#pragma unroll
        for (int kk = 0; kk < 4; kk++)
            *(float4*)(As + e * 72 + q4 * 16 + 4 * kk) =
                *(const float4*)(Tb + e * 1024 + j0 + q4 * 16 + 4 * kk);
        __syncthreads();
#pragma unroll
        for (int nt = 0; nt < 4; nt++) {
            float acc[4] = {0.f, 0.f, 0.f, 0.f};
            int jb = jh * 32 + nt * 8;
#pragma unroll
            for (int k = 0; k < 8; k++) {
                unsigned bh[2] = {f2tf(As[(8 * k + tig) * 72 + jb + gid]),
                                  f2tf(As[(8 * k + tig + 4) * 72 + jb + gid])};
                mma8(acc, ar[k], bh);
            }
            int c0 = cs * 16 + gid, jj = jb + 2 * tig;
            float bias0 = sb[c0] * swv + wbv, bias1 = sb[c0 + 8] * swv + wbv;
            Ds[jj * 68 + c0] = acc[0] + bias0;
            Ds[(jj + 1) * 68 + c0] = acc[1] + bias0;
            Ds[jj * 68 + c0 + 8] = acc[2] + bias1;
            Ds[(jj + 1) * 68 + c0 + 8] = acc[3] + bias1;
        }
        __syncthreads();
        {
            int j = t >> 2, h = t & 3;
#pragma unroll
            for (int kk = 0; kk < 4; kk++) {
                float4 v = *(const float4*)(Ds + j * 68 + h * 16 + 4 * kk);
                ls += v.x + v.y + v.z + v.w;
                lq += v.x * v.x + v.y * v.y + v.z * v.z + v.w * v.w;
                *(float4*)(ob + (j0 + j) * 64 + h * 16 + 4 * kk) = v;
            }
        }
        __syncthreads();
    }
#pragma unroll
    for (int o = 16; o >= 1; o >>= 1) {
        ls += __shfl_xor_sync(0xffffffffu, ls, o);
        lq += __shfl_xor_sync(0xffffffffu, lq, o);
    }
    if (lane == 0) { atomicAdd(&g_sum[oc], ls); atomicAdd(&g_sumsq[oc], lq); }
}

__global__ void k4(const float* __restrict__ gamma, const float* __restrict__ bnb) {
    int t = threadIdx.x;
    if (t < 64) {
        float m = g_sum[t] / CNT;
        float v = g_sumsq[t] / CNT - m * m;
        float sc = gamma[t] * rsqrtf(v + 1e-5f);
        g_scale[t] = sc;
        g_shift[t] = bnb[t] - m * sc;
    }
}

__global__ __launch_bounds__(256) void k5(const float* __restrict__ x, float* __restrict__ out) {
    long i4 = (long)blockIdx.x * 256 + threadIdx.x;
    int ch = (int)(i4 >> 14) & 63;
    float sc = __ldg(&g_scale[ch]), sh = __ldg(&g_shift[ch]);
    float4 wv = ((const float4*)out)[i4];
    float4 xv = ((const float4*)x)[i4];
    float4 o;
    o.x = wv.x * sc + sh + xv.x;
    o.y = wv.y * sc + sh + xv.y;
    o.z = wv.z * sc + sh + xv.z;
    o.w = wv.w * sc + sh + xv.w;
    ((float4*)out)[i4] = o;
}

extern "C" void kernel_launch(void* const* d_in, const int* in_sizes, int n_in,
                              void* d_out, int out_size) {
    const float* x  = (const float*)d_in[0];
    const float* tw = (const float*)d_in[1];
    const float* tb = (const float*)d_in[2];
    const float* pw = (const float*)d_in[3];
    const float* pb = (const float*)d_in[4];
    const float* gw = (const float*)d_in[5];
    const float* gb = (const float*)d_in[6];
    const float* ww = (const float*)d_in[7];
    const float* wb = (const float*)d_in[8];
    const float* gamma = (const float*)d_in[9];
    const float* bnb = (const float*)d_in[10];
    float* out = (float*)d_out;
    k0<<<64, 256>>>();
    kG<<<dim3(128, 4), 256>>>(x);
    kT<<<dim3(2, 256), 256>>>(x, ww);
    k2<<<4, 256>>>(tw, tb, pw, pb, gw, gb, ww);
    kB<<<dim3(64, 4), 256>>>(wb, out);
    k4<<<1, 64>>>(gamma, bnb);
    k5<<<16384, 256>>>(x, out);
}

// round 5
// speedup vs baseline: 1.9593x; 1.0505x over previous
#include <cuda_runtime.h>
#include <math.h>

#define CNT 262144.0f

__device__ float g_T[4L*64*65536];   // [b][oc][e*1024+j]
__device__ float g_Gx[4*64*64];
__device__ float g_Gq[4*64*64];
__device__ float g_sx[4*64];
__device__ float g_R[4*64*64];       // R[c][e]
__device__ float g_beta[4*64];
__device__ float g_Sw[64];
__device__ float g_sum[64], g_sumsq[64];
__device__ float g_scale[64], g_shift[64];

__device__ __forceinline__ unsigned f2tf(float f) {
    unsigned u; asm("cvt.rna.tf32.f32 %0, %1;" : "=r"(u) : "f"(f)); return u;
}
__device__ __forceinline__ void mma8(float* c, const unsigned* a, const unsigned* b) {
    asm("mma.sync.aligned.m16n8k8.row.col.f32.tf32.tf32.f32 "
        "{%0,%1,%2,%3},{%4,%5,%6,%7},{%8,%9},{%0,%1,%2,%3};"
        : "+f"(c[0]), "+f"(c[1]), "+f"(c[2]), "+f"(c[3])
        : "r"(a[0]), "r"(a[1]), "r"(a[2]), "r"(a[3]), "r"(b[0]), "r"(b[1]));
}

__global__ void k0() {
    int i = blockIdx.x * 256 + threadIdx.x;
    if (i < 16384) { g_Gx[i] = 0.f; g_Gq[i] = 0.f; }
    if (i < 256) g_sx[i] = 0.f;
    if (i < 64) { g_sum[i] = 0.f; g_sumsq[i] = 0.f; }
}

// Gram: Gx = Xhi Xhi^T, Gq = Xhi Xlo^T; plus column sums.
__global__ __launch_bounds__(256) void kG(const float* __restrict__ x) {
    __shared__ __align__(16) float Xs[64 * 132];
    const int b = blockIdx.y, t = threadIdx.x, w = t >> 5, lane = t & 31;
    const int gid = lane >> 2, tig = lane & 3;
    const int rs = w & 3, cg = w >> 2;
    const int cp = t >> 2, q = t & 3;
    float P[4][4], Q[4][4];
#pragma unroll
    for (int u = 0; u < 4; u++)
#pragma unroll
        for (int i = 0; i < 4; i++) { P[u][i] = 0.f; Q[u][i] = 0.f; }
    float sx = 0.f;
    for (int tt = 0; tt < 4; tt++) {
        int n0 = (blockIdx.x * 4 + tt) * 128;
        const float* src = x + ((long)(b * 64 + cp)) * 65536 + n0 + q * 32;
#pragma unroll
        for (int k = 0; k < 8; k++) {
            float4 v = *(const float4*)(src + 4 * k);
            sx += v.x + v.y + v.z + v.w;
            *(float4*)(Xs + cp * 132 + q * 32 + 4 * k) = v;
        }
        __syncthreads();
        for (int ks = 0; ks < 16; ks++) {
            const int col = 8 * ks + tig, e0 = rs * 16 + gid;
            unsigned ah[4];
            ah[0] = f2tf(Xs[e0 * 132 + col]);
            ah[1] = f2tf(Xs[(e0 + 8) * 132 + col]);
            ah[2] = f2tf(Xs[e0 * 132 + col + 4]);
            ah[3] = f2tf(Xs[(e0 + 8) * 132 + col + 4]);
#pragma unroll
            for (int u = 0; u < 4; u++) {
                int ep = cg * 32 + 8 * u + gid;
                float f0 = Xs[ep * 132 + col], f1 = Xs[ep * 132 + col + 4];
                unsigned bh[2] = {f2tf(f0), f2tf(f1)};
                unsigned bl[2] = {f2tf(f0 - __uint_as_float(bh[0])),
                                  f2tf(f1 - __uint_as_float(bh[1]))};
                mma8(P[u], ah, bh);
                mma8(Q[u], ah, bl);
            }
        }
        __syncthreads();
    }
    float* Gp = g_Gx + b * 4096;
    float* Gq = g_Gq + b * 4096;
#pragma unroll
    for (int u = 0; u < 4; u++) {
        int r0 = rs * 16 + gid, c0 = cg * 32 + 8 * u + 2 * tig;
        atomicAdd(&Gp[r0 * 64 + c0], P[u][0]);
        atomicAdd(&Gp[r0 * 64 + c0 + 1], P[u][1]);
        atomicAdd(&Gp[(r0 + 8) * 64 + c0], P[u][2]);
        atomicAdd(&Gp[(r0 + 8) * 64 + c0 + 1], P[u][3]);
        atomicAdd(&Gq[r0 * 64 + c0], Q[u][0]);
        atomicAdd(&Gq[r0 * 64 + c0 + 1], Q[u][1]);
        atomicAdd(&Gq[(r0 + 8) * 64 + c0], Q[u][2]);
        atomicAdd(&Gq[(r0 + 8) * 64 + c0 + 1], Q[u][3]);
    }
    sx += __shfl_down_sync(0xffffffffu, sx, 1);
    sx += __shfl_down_sync(0xffffffffu, sx, 2);
    if (q == 0) atomicAdd(&g_sx[b * 64 + cp], sx);
}

// T[b][oc][e*1024+j] = sum_ch Wc[oc][ch] * x[b][e][ch*1024+j]
__global__ __launch_bounds__(256) void kT(const float* __restrict__ x,
                                          const float* __restrict__ ww) {
    __shared__ __align__(16) float Xs[64 * 132];
    const int be = blockIdx.y;
    const int b = be >> 6, e = be & 63;
    const int t = threadIdx.x, w = t >> 5, lane = t & 31;
    const int gid = lane >> 2, tig = lane & 3;
    const int rs = w & 3, jh = w >> 2;
    const int ch_ld = t >> 2, q = t & 3;
    unsigned aw[8][4];
#pragma unroll
    for (int k = 0; k < 8; k++) {
        int r = rs * 16 + gid, c = 8 * k + tig;
        aw[k][0] = f2tf(ww[r * 64 + c]);
        aw[k][1] = f2tf(ww[(r + 8) * 64 + c]);
        aw[k][2] = f2tf(ww[r * 64 + c + 4]);
        aw[k][3] = f2tf(ww[(r + 8) * 64 + c + 4]);
    }
    const float* xe = x + (long)be * 65536;
    for (int tt = 0; tt < 4; tt++) {
        int j0 = blockIdx.x * 512 + tt * 128;
        const float* src = xe + ch_ld * 1024 + j0 + q * 32;
#pragma unroll
        for (int k = 0; k < 8; k++)
            *(float4*)(Xs + ch_ld * 132 + q * 32 + 4 * k) = *(const float4*)(src + 4 * k);
        __syncthreads();
#pragma unroll
        for (int half = 0; half < 2; half++) {
            float acc[4][4];
#pragma unroll
            for (int u = 0; u < 4; u++)
#pragma unroll
                for (int i = 0; i < 4; i++) acc[u][i] = 0.f;
            int nb = jh * 64 + half * 32;
#pragma unroll
            for (int k = 0; k < 8; k++) {
#pragma unroll
                for (int u = 0; u < 4; u++) {
                    int nn = nb + 8 * u + gid;
                    unsigned bh[2] = {f2tf(Xs[(8 * k + tig) * 132 + nn]),
                                      f2tf(Xs[(8 * k + tig + 4) * 132 + nn])};
                    mma8(acc[u], aw[k], bh);
                }
            }
#pragma unroll
            for (int u = 0; u < 4; u++) {
                int oc = rs * 16 + gid, nn = nb + 8 * u + 2 * tig;
                float* d0 = g_T + ((long)(b * 64 + oc)) * 65536 + e * 1024 + j0 + nn;
                *(float2*)d0 = make_float2(acc[u][0], acc[u][1]);
                *(float2*)(d0 + 8L * 65536) = make_float2(acc[u][2], acc[u][3]);
            }
        }
        __syncthreads();
    }
}

// f = Pw G Tw^T + rank1, softmax, R, beta, Sw  (G = Gx + Gq + Gq^T)
// All operands staged through shared; no rolled global-latency loops.
__global__ __launch_bounds__(256) void k2(
    const float* __restrict__ tw, const float* __restrict__ tb,
    const float* __restrict__ pw, const float* __restrict__ pb,
    const float* __restrict__ gw, const float* __restrict__ gb,
    const float* __restrict__ ww) {
    __shared__ float A[64 * 68], Bf[64 * 68];
    __shared__ float s_sx[64], s_tsx[64], s_psx[64], s_tb[64], s_pb[64], s_gb[64];
    const int b = blockIdx.x, t = threadIdx.x;
    const int ty = t >> 4, tx = t & 15;
    if (t < 64) { s_sx[t] = g_sx[b*64+t]; s_tb[t] = tb[t]; s_pb[t] = pb[t]; s_gb[t] = gb[t]; }
    // stage A = Tw^T  (A[e*68+d] = tw[d][e])
    for (int idx = t; idx < 4096; idx += 256) A[(idx & 63) * 68 + (idx >> 6)] = tw[idx];
    // stage Bf = Gsym
    {
        const float* Gx = g_Gx + b * 4096;
        const float* Gq = g_Gq + b * 4096;
        for (int idx = t; idx < 4096; idx += 256) {
            int r = idx >> 6, c = idx & 63;
            Bf[r * 68 + c] = Gx[idx] + Gq[idx] + Gq[c * 64 + r];
        }
    }
    __syncthreads();
    if (t < 64) {
        float a1 = 0.f;
#pragma unroll 16
        for (int e = 0; e < 64; e++) a1 += A[e * 68 + t] * s_sx[e];
        s_tsx[t] = a1;
    }
    // GEMM1: M1[r][d] = sum_e Gsym[e][r] * TwT[e][d]   (Gsym symmetric)
    float acc[4][4];
#pragma unroll
    for (int i = 0; i < 4; i++)
#pragma unroll
        for (int j = 0; j < 4; j++) acc[i][j] = 0.f;
#pragma unroll 8
    for (int e = 0; e < 64; e++) {
        float4 av = *(const float4*)(Bf + e * 68 + 4 * ty);
        float4 bv = *(const float4*)(A + e * 68 + 4 * tx);
        float aa[4]={av.x,av.y,av.z,av.w}, bb[4]={bv.x,bv.y,bv.z,bv.w};
#pragma unroll
        for (int i = 0; i < 4; i++)
#pragma unroll
            for (int j = 0; j < 4; j++) acc[i][j] += aa[i]*bb[j];
    }
    __syncthreads();
    // Bf <- M1 ; A <- Pw^T
#pragma unroll
    for (int i = 0; i < 4; i++)
#pragma unroll
        for (int j = 0; j < 4; j++) Bf[(4*ty+i)*68 + 4*tx+j] = acc[i][j];
    for (int idx = t; idx < 4096; idx += 256) A[(idx & 63) * 68 + (idx >> 6)] = pw[idx];
    __syncthreads();
    if (t < 64) {
        float a2 = 0.f;
#pragma unroll 16
        for (int e = 0; e < 64; e++) a2 += A[e * 68 + t] * s_sx[e];
        s_psx[t] = a2;
    }
    // GEMM2: f[c][d] = sum_e PwT[e][c] * M1[e][d]
#pragma unroll
    for (int i = 0; i < 4; i++)
#pragma unroll
        for (int j = 0; j < 4; j++) acc[i][j] = 0.f;
#pragma unroll 8
    for (int e = 0; e < 64; e++) {
        float4 av = *(const float4*)(A + e*68 + 4*ty);
        float4 bv = *(const float4*)(Bf + e*68 + 4*tx);
        float aa[4]={av.x,av.y,av.z,av.w}, bb[4]={bv.x,bv.y,bv.z,bv.w};
#pragma unroll
        for (int i = 0; i < 4; i++)
#pragma unroll
            for (int j = 0; j < 4; j++) acc[i][j] += aa[i]*bb[j];
    }
    __syncthreads();
#pragma unroll
    for (int i = 0; i < 4; i++)
#pragma unroll
        for (int j = 0; j < 4; j++) {
            int c = 4*ty+i, d = 4*tx+j;
            Bf[c*68+d] = acc[i][j] + s_pb[c]*(s_tsx[d] + 65536.f*s_tb[d]) + s_psx[c]*s_tb[d];
        }
    __syncthreads();
    { // softmax rows of Bf -> attn^T into A[d][c]
        const int w = t >> 5, lane = t & 31;
        for (int c = w*8; c < w*8+8; c++) {
            float v0 = Bf[c*68+lane], v1 = Bf[c*68+32+lane];
            float m = fmaxf(v0, v1);
#pragma unroll
            for (int o = 16; o >= 1; o >>= 1) m = fmaxf(m, __shfl_xor_sync(0xffffffffu, m, o));
            float e0 = __expf(v0-m), e1 = __expf(v1-m), s = e0+e1;
#pragma unroll
            for (int o = 16; o >= 1; o >>= 1) s += __shfl_xor_sync(0xffffffffu, s, o);
            float inv = 1.f/s;
            A[lane*68+c] = e0*inv;
            A[(lane+32)*68+c] = e1*inv;
        }
    }
    __syncthreads();
    // stage Bf <- gw rows (Bf[d*68+e] = gw[d][e])
    for (int idx = t; idx < 4096; idx += 256) Bf[(idx >> 6) * 68 + (idx & 63)] = gw[idx];
    __syncthreads();
    if (t < 64) {
        float bs = 0.f;
#pragma unroll 16
        for (int d = 0; d < 64; d++) bs += A[d*68+t]*s_gb[d];
        g_beta[b*64+t] = bs;
    }
    // GEMM3: R[c][e] = sum_d attnT[d][c] * gw[d][e]
#pragma unroll
    for (int i = 0; i < 4; i++)
#pragma unroll
        for (int j = 0; j < 4; j++) acc[i][j] = 0.f;
#pragma unroll 8
    for (int d = 0; d < 64; d++) {
        float4 av = *(const float4*)(Bf + d*68 + 4*ty);
        float4 bv = *(const float4*)(A + d*68 + 4*tx);
        float aa[4]={av.x,av.y,av.z,av.w}, bb[4]={bv.x,bv.y,bv.z,bv.w};
#pragma unroll
        for (int i = 0; i < 4; i++)
#pragma unroll
            for (int j = 0; j < 4; j++) acc[i][j] += aa[i]*bb[j];
    }
#pragma unroll
    for (int i = 0; i < 4; i++)
#pragma unroll
        for (int j = 0; j < 4; j++)
            g_R[b*4096 + (4*tx+j)*64 + (4*ty+i)] = acc[i][j];
    if (b == 0 && t < 64) {
        float s = 0.f;
        const float4* wr = (const float4*)(ww + t * 64);
#pragma unroll
        for (int k = 0; k < 16; k++) {
            float4 v = wr[k];
            s += v.x + v.y + v.z + v.w;
        }
        g_Sw[t] = s;
    }
}

// wy[b][oc][j*64+c] = sum_e R[c][e]*T[b][oc][e*1024+j] + beta[c]*Sw[oc] + wb[oc]
__global__ __launch_bounds__(256) void kB(const float* __restrict__ wbias,
                                          float* __restrict__ out) {
    __shared__ __align__(16) float As[64 * 72];
    __shared__ __align__(16) float Ds[64 * 68];
    __shared__ float sb[64];
    const int oc = blockIdx.x, b = blockIdx.y, bz = blockIdx.z, t = threadIdx.x;
    const int w = t >> 5, lane = t & 31, gid = lane >> 2, tig = lane & 3;
    const int cs = w & 3, jh = w >> 2;
    if (t < 64) sb[t] = g_beta[b * 64 + t];
    const float swv = g_Sw[oc], wbv = wbias[oc];
    unsigned ar[8][4];
    const float* Rb = g_R + b * 4096;
#pragma unroll
    for (int k = 0; k < 8; k++) {
        int r = cs * 16 + gid, c = 8 * k + tig;
        ar[k][0] = f2tf(Rb[r * 64 + c]);
        ar[k][1] = f2tf(Rb[(r + 8) * 64 + c]);
        ar[k][2] = f2tf(Rb[r * 64 + c + 4]);
        ar[k][3] = f2tf(Rb[(r + 8) * 64 + c + 4]);
    }
    const float* Tb = g_T + ((long)(b * 64 + oc)) * 65536;
    float* ob = out + ((long)(b * 64 + oc)) * 65536;
    float ls = 0.f, lq = 0.f;
    const int e = t >> 2, q4 = t & 3;
    __syncthreads();
    for (int jt = bz * 8; jt < bz * 8 + 8; jt++) {
        int j0 = jt * 64;
#pragma unroll
        for (int kk = 0; kk < 4; kk++)
            *(float4*)(As + e * 72 + q4 * 16 + 4 * kk) =
                *(const float4*)(Tb + e * 1024 + j0 + q4 * 16 + 4 * kk);
        __syncthreads();
#pragma unroll
        for (int nt = 0; nt < 4; nt++) {
            float acc[4] = {0.f, 0.f, 0.f, 0.f};
            int jb = jh * 32 + nt * 8;
#pragma unroll
            for (int k = 0; k < 8; k++) {
                unsigned bh[2] = {f2tf(As[(8 * k + tig) * 72 + jb + gid]),
                                  f2tf(As[(8 * k + tig + 4) * 72 + jb + gid])};
                mma8(acc, ar[k], bh);
            }
            int c0 = cs * 16 + gid, jj = jb + 2 * tig;
            float bias0 = sb[c0] * swv + wbv, bias1 = sb[c0 + 8] * swv + wbv;
            Ds[jj * 68 + c0] = acc[0] + bias0;
            Ds[(jj + 1) * 68 + c0] = acc[1] + bias0;
            Ds[jj * 68 + c0 + 8] = acc[2] + bias1;
            Ds[(jj + 1) * 68 + c0 + 8] = acc[3] + bias1;
        }
        __syncthreads();
        {
            int j = t >> 2, h = t & 3;
#pragma unroll
            for (int kk = 0; kk < 4; kk++) {
                float4 v = *(const float4*)(Ds + j * 68 + h * 16 + 4 * kk);
                ls += v.x + v.y + v.z + v.w;
                lq += v.x * v.x + v.y * v.y + v.z * v.z + v.w * v.w;
                *(float4*)(ob + (j0 + j) * 64 + h * 16 + 4 * kk) = v;
            }
        }
        __syncthreads();
    }
#pragma unroll
    for (int o = 16; o >= 1; o >>= 1) {
        ls += __shfl_xor_sync(0xffffffffu, ls, o);
        lq += __shfl_xor_sync(0xffffffffu, lq, o);
    }
    if (lane == 0) { atomicAdd(&g_sum[oc], ls); atomicAdd(&g_sumsq[oc], lq); }
}

__global__ void k4(const float* __restrict__ gamma, const float* __restrict__ bnb) {
    int t = threadIdx.x;
    if (t < 64) {
        float m = g_sum[t] / CNT;
        float v = g_sumsq[t] / CNT - m * m;
        float sc = gamma[t] * rsqrtf(v + 1e-5f);
        g_scale[t] = sc;
        g_shift[t] = bnb[t] - m * sc;
    }
}

__global__ __launch_bounds__(256) void k5(const float* __restrict__ x, float* __restrict__ out) {
    long i4 = (long)blockIdx.x * 256 + threadIdx.x;
    int ch = (int)(i4 >> 14) & 63;
    float sc = __ldg(&g_scale[ch]), sh = __ldg(&g_shift[ch]);
    float4 wv = ((const float4*)out)[i4];
    float4 xv = ((const float4*)x)[i4];
    float4 o;
    o.x = wv.x * sc + sh + xv.x;
    o.y = wv.y * sc + sh + xv.y;
    o.z = wv.z * sc + sh + xv.z;
    o.w = wv.w * sc + sh + xv.w;
    ((float4*)out)[i4] = o;
}

extern "C" void kernel_launch(void* const* d_in, const int* in_sizes, int n_in,
                              void* d_out, int out_size) {
    const float* x  = (const float*)d_in[0];
    const float* tw = (const float*)d_in[1];
    const float* tb = (const float*)d_in[2];
    const float* pw = (const float*)d_in[3];
    const float* pb = (const float*)d_in[4];
    const float* gw = (const float*)d_in[5];
    const float* gb = (const float*)d_in[6];
    const float* ww = (const float*)d_in[7];
    const float* wb = (const float*)d_in[8];
    const float* gamma = (const float*)d_in[9];
    const float* bnb = (const float*)d_in[10];
    float* out = (float*)d_out;
    k0<<<64, 256>>>();
    kG<<<dim3(128, 4), 256>>>(x);
    kT<<<dim3(2, 256), 256>>>(x, ww);
    k2<<<4, 256>>>(tw, tb, pw, pb, gw, gb, ww);
    kB<<<dim3(64, 4, 2), 256>>>(wb, out);
    k4<<<1, 64>>>(gamma, bnb);
    k5<<<16384, 256>>>(x, out);
}

// round 6
// speedup vs baseline: 2.1562x; 1.1005x over previous
#include <cuda_runtime.h>
#include <math.h>

#define CNT 262144.0f

__device__ float g_T[4L*64*65536];   // [b][oc][e*1024+j]
__device__ float g_Gx[4*64*64];
__device__ float g_Gq[4*64*64];
__device__ float g_sx[4*64];
__device__ float g_R[4*64*64];       // R[c][e]
__device__ float g_beta[4*64];
__device__ float g_Sw[64];
__device__ float g_sum[64], g_sumsq[64];
__device__ float g_scale[64], g_shift[64];

__device__ __forceinline__ unsigned f2tf(float f) {
    unsigned u; asm("cvt.rna.tf32.f32 %0, %1;" : "=r"(u) : "f"(f)); return u;
}
__device__ __forceinline__ void mma8(float* c, const unsigned* a, const unsigned* b) {
    asm("mma.sync.aligned.m16n8k8.row.col.f32.tf32.tf32.f32 "
        "{%0,%1,%2,%3},{%4,%5,%6,%7},{%8,%9},{%0,%1,%2,%3};"
        : "+f"(c[0]), "+f"(c[1]), "+f"(c[2]), "+f"(c[3])
        : "r"(a[0]), "r"(a[1]), "r"(a[2]), "r"(a[3]), "r"(b[0]), "r"(b[1]));
}

__global__ void k0() {
    int i = blockIdx.x * 256 + threadIdx.x;
    if (i < 16384) { g_Gx[i] = 0.f; g_Gq[i] = 0.f; }
    if (i < 256) g_sx[i] = 0.f;
    if (i < 64) { g_sum[i] = 0.f; g_sumsq[i] = 0.f; }
}

// Gram: Gx = Xhi Xhi^T, Gq = Xhi Xlo^T; plus column sums.
__global__ __launch_bounds__(256) void kG(const float* __restrict__ x) {
    __shared__ __align__(16) float Xs[64 * 132];
    const int b = blockIdx.y, t = threadIdx.x, w = t >> 5, lane = t & 31;
    const int gid = lane >> 2, tig = lane & 3;
    const int rs = w & 3, cg = w >> 2;
    const int cp = t >> 2, q = t & 3;
    float P[4][4], Q[4][4];
#pragma unroll
    for (int u = 0; u < 4; u++)
#pragma unroll
        for (int i = 0; i < 4; i++) { P[u][i] = 0.f; Q[u][i] = 0.f; }
    float sx = 0.f;
    for (int tt = 0; tt < 4; tt++) {
        int n0 = (blockIdx.x * 4 + tt) * 128;
        const float* src = x + ((long)(b * 64 + cp)) * 65536 + n0 + q * 32;
#pragma unroll
        for (int k = 0; k < 8; k++) {
            float4 v = *(const float4*)(src + 4 * k);
            sx += v.x + v.y + v.z + v.w;
            *(float4*)(Xs + cp * 132 + q * 32 + 4 * k) = v;
        }
        __syncthreads();
        for (int ks = 0; ks < 16; ks++) {
            const int col = 8 * ks + tig, e0 = rs * 16 + gid;
            unsigned ah[4];
            ah[0] = f2tf(Xs[e0 * 132 + col]);
            ah[1] = f2tf(Xs[(e0 + 8) * 132 + col]);
            ah[2] = f2tf(Xs[e0 * 132 + col + 4]);
            ah[3] = f2tf(Xs[(e0 + 8) * 132 + col + 4]);
#pragma unroll
            for (int u = 0; u < 4; u++) {
                int ep = cg * 32 + 8 * u + gid;
                float f0 = Xs[ep * 132 + col], f1 = Xs[ep * 132 + col + 4];
                unsigned bh[2] = {f2tf(f0), f2tf(f1)};
                unsigned bl[2] = {f2tf(f0 - __uint_as_float(bh[0])),
                                  f2tf(f1 - __uint_as_float(bh[1]))};
                mma8(P[u], ah, bh);
                mma8(Q[u], ah, bl);
            }
        }
        __syncthreads();
    }
    float* Gp = g_Gx + b * 4096;
    float* Gq = g_Gq + b * 4096;
#pragma unroll
    for (int u = 0; u < 4; u++) {
        int r0 = rs * 16 + gid, c0 = cg * 32 + 8 * u + 2 * tig;
        atomicAdd(&Gp[r0 * 64 + c0], P[u][0]);
        atomicAdd(&Gp[r0 * 64 + c0 + 1], P[u][1]);
        atomicAdd(&Gp[(r0 + 8) * 64 + c0], P[u][2]);
        atomicAdd(&Gp[(r0 + 8) * 64 + c0 + 1], P[u][3]);
        atomicAdd(&Gq[r0 * 64 + c0], Q[u][0]);
        atomicAdd(&Gq[r0 * 64 + c0 + 1], Q[u][1]);
        atomicAdd(&Gq[(r0 + 8) * 64 + c0], Q[u][2]);
        atomicAdd(&Gq[(r0 + 8) * 64 + c0 + 1], Q[u][3]);
    }
    sx += __shfl_down_sync(0xffffffffu, sx, 1);
    sx += __shfl_down_sync(0xffffffffu, sx, 2);
    if (q == 0) atomicAdd(&g_sx[b * 64 + cp], sx);
}

// T[b][oc][e*1024+j] = sum_ch Wc[oc][ch] * x[b][e][ch*1024+j]
__global__ __launch_bounds__(256) void kT(const float* __restrict__ x,
                                          const float* __restrict__ ww) {
    __shared__ __align__(16) float Xs[64 * 132];
    const int be = blockIdx.y;
    const int b = be >> 6, e = be & 63;
    const int t = threadIdx.x, w = t >> 5, lane = t & 31;
    const int gid = lane >> 2, tig = lane & 3;
    const int rs = w & 3, jh = w >> 2;
    const int ch_ld = t >> 2, q = t & 3;
    unsigned aw[8][4];
#pragma unroll
    for (int k = 0; k < 8; k++) {
        int r = rs * 16 + gid, c = 8 * k + tig;
        aw[k][0] = f2tf(ww[r * 64 + c]);
        aw[k][1] = f2tf(ww[(r + 8) * 64 + c]);
        aw[k][2] = f2tf(ww[r * 64 + c + 4]);
        aw[k][3] = f2tf(ww[(r + 8) * 64 + c + 4]);
    }
    const float* xe = x + (long)be * 65536;
    for (int tt = 0; tt < 4; tt++) {
        int j0 = blockIdx.x * 512 + tt * 128;
        const float* src = xe + ch_ld * 1024 + j0 + q * 32;
#pragma unroll
        for (int k = 0; k < 8; k++)
            *(float4*)(Xs + ch_ld * 132 + q * 32 + 4 * k) = *(const float4*)(src + 4 * k);
        __syncthreads();
#pragma unroll
        for (int half = 0; half < 2; half++) {
            float acc[4][4];
#pragma unroll
            for (int u = 0; u < 4; u++)
#pragma unroll
                for (int i = 0; i < 4; i++) acc[u][i] = 0.f;
            int nb = jh * 64 + half * 32;
#pragma unroll
            for (int k = 0; k < 8; k++) {
#pragma unroll
                for (int u = 0; u < 4; u++) {
                    int nn = nb + 8 * u + gid;
                    unsigned bh[2] = {f2tf(Xs[(8 * k + tig) * 132 + nn]),
                                      f2tf(Xs[(8 * k + tig + 4) * 132 + nn])};
                    mma8(acc[u], aw[k], bh);
                }
            }
#pragma unroll
            for (int u = 0; u < 4; u++) {
                int oc = rs * 16 + gid, nn = nb + 8 * u + 2 * tig;
                float* d0 = g_T + ((long)(b * 64 + oc)) * 65536 + e * 1024 + j0 + nn;
                *(float2*)d0 = make_float2(acc[u][0], acc[u][1]);
                *(float2*)(d0 + 8L * 65536) = make_float2(acc[u][2], acc[u][3]);
            }
        }
        __syncthreads();
    }
}

// f = Pw G Tw^T + rank1, softmax, R, beta, Sw  (G = Gx + Gq + Gq^T)
// 512 threads: each computes a 4x2 sub-tile; more warps to hide LDS latency.
__global__ __launch_bounds__(512) void k2(
    const float* __restrict__ tw, const float* __restrict__ tb,
    const float* __restrict__ pw, const float* __restrict__ pb,
    const float* __restrict__ gw, const float* __restrict__ gb,
    const float* __restrict__ ww) {
    __shared__ float A[64 * 68], Bf[64 * 68];
    __shared__ float s_sx[64], s_tsx[64], s_psx[64], s_tb[64], s_pb[64], s_gb[64];
    const int b = blockIdx.x, t = threadIdx.x;
    const int ty = t >> 5, tx = t & 31;
    if (t < 64) { s_sx[t] = g_sx[b*64+t]; s_tb[t] = tb[t]; s_pb[t] = pb[t]; s_gb[t] = gb[t]; }
    for (int idx = t; idx < 4096; idx += 512) A[(idx & 63) * 68 + (idx >> 6)] = tw[idx];
    {
        const float* Gx = g_Gx + b * 4096;
        const float* Gq = g_Gq + b * 4096;
        for (int idx = t; idx < 4096; idx += 512) {
            int r = idx >> 6, c = idx & 63;
            Bf[r * 68 + c] = Gx[idx] + Gq[idx] + Gq[c * 64 + r];
        }
    }
    __syncthreads();
    if (t < 64) {
        float a1 = 0.f;
#pragma unroll 16
        for (int e = 0; e < 64; e++) a1 += A[e * 68 + t] * s_sx[e];
        s_tsx[t] = a1;
    }
    // GEMM1: M1[r][d] = sum_e Gsym[e][r] * TwT[e][d]
    float acc[4][2];
#pragma unroll
    for (int i = 0; i < 4; i++) { acc[i][0] = 0.f; acc[i][1] = 0.f; }
#pragma unroll 8
    for (int e = 0; e < 64; e++) {
        float4 av = *(const float4*)(Bf + e * 68 + 4 * ty);
        float2 bv = *(const float2*)(A + e * 68 + 2 * tx);
        acc[0][0] += av.x*bv.x; acc[0][1] += av.x*bv.y;
        acc[1][0] += av.y*bv.x; acc[1][1] += av.y*bv.y;
        acc[2][0] += av.z*bv.x; acc[2][1] += av.z*bv.y;
        acc[3][0] += av.w*bv.x; acc[3][1] += av.w*bv.y;
    }
    __syncthreads();
#pragma unroll
    for (int i = 0; i < 4; i++) {
        Bf[(4*ty+i)*68 + 2*tx]     = acc[i][0];
        Bf[(4*ty+i)*68 + 2*tx + 1] = acc[i][1];
    }
    for (int idx = t; idx < 4096; idx += 512) A[(idx & 63) * 68 + (idx >> 6)] = pw[idx];
    __syncthreads();
    if (t < 64) {
        float a2 = 0.f;
#pragma unroll 16
        for (int e = 0; e < 64; e++) a2 += A[e * 68 + t] * s_sx[e];
        s_psx[t] = a2;
    }
    // GEMM2: f[c][d] = sum_e PwT[e][c] * M1[e][d]
#pragma unroll
    for (int i = 0; i < 4; i++) { acc[i][0] = 0.f; acc[i][1] = 0.f; }
#pragma unroll 8
    for (int e = 0; e < 64; e++) {
        float4 av = *(const float4*)(A + e*68 + 4*ty);
        float2 bv = *(const float2*)(Bf + e*68 + 2*tx);
        acc[0][0] += av.x*bv.x; acc[0][1] += av.x*bv.y;
        acc[1][0] += av.y*bv.x; acc[1][1] += av.y*bv.y;
        acc[2][0] += av.z*bv.x; acc[2][1] += av.z*bv.y;
        acc[3][0] += av.w*bv.x; acc[3][1] += av.w*bv.y;
    }
    __syncthreads();
#pragma unroll
    for (int i = 0; i < 4; i++)
#pragma unroll
        for (int j = 0; j < 2; j++) {
            int c = 4*ty+i, d = 2*tx+j;
            Bf[c*68+d] = acc[i][j] + s_pb[c]*(s_tsx[d] + 65536.f*s_tb[d]) + s_psx[c]*s_tb[d];
        }
    __syncthreads();
    { // softmax rows of Bf -> attn^T into A[d][c]; 16 warps x 4 rows
        const int w = t >> 5, lane = t & 31;
        for (int c = w*4; c < w*4+4; c++) {
            float v0 = Bf[c*68+lane], v1 = Bf[c*68+32+lane];
            float m = fmaxf(v0, v1);
#pragma unroll
            for (int o = 16; o >= 1; o >>= 1) m = fmaxf(m, __shfl_xor_sync(0xffffffffu, m, o));
            float e0 = __expf(v0-m), e1 = __expf(v1-m), s = e0+e1;
#pragma unroll
            for (int o = 16; o >= 1; o >>= 1) s += __shfl_xor_sync(0xffffffffu, s, o);
            float inv = 1.f/s;
            A[lane*68+c] = e0*inv;
            A[(lane+32)*68+c] = e1*inv;
        }
    }
    __syncthreads();
    for (int idx = t; idx < 4096; idx += 512) Bf[(idx >> 6) * 68 + (idx & 63)] = gw[idx];
    __syncthreads();
    if (t < 64) {
        float bs = 0.f;
#pragma unroll 16
        for (int d = 0; d < 64; d++) bs += A[d*68+t]*s_gb[d];
        g_beta[b*64+t] = bs;
    }
    // GEMM3: R[c][e] = sum_d attnT[d][c] * gw[d][e]
#pragma unroll
    for (int i = 0; i < 4; i++) { acc[i][0] = 0.f; acc[i][1] = 0.f; }
#pragma unroll 8
    for (int d = 0; d < 64; d++) {
        float4 av = *(const float4*)(Bf + d*68 + 4*ty);
        float2 bv = *(const float2*)(A + d*68 + 2*tx);
        acc[0][0] += av.x*bv.x; acc[0][1] += av.x*bv.y;
        acc[1][0] += av.y*bv.x; acc[1][1] += av.y*bv.y;
        acc[2][0] += av.z*bv.x; acc[2][1] += av.z*bv.y;
        acc[3][0] += av.w*bv.x; acc[3][1] += av.w*bv.y;
    }
#pragma unroll
    for (int i = 0; i < 4; i++)
#pragma unroll
        for (int j = 0; j < 2; j++)
            g_R[b*4096 + (2*tx+j)*64 + (4*ty+i)] = acc[i][j];
    if (b == 0 && t < 64) {
        float s = 0.f;
        const float4* wr = (const float4*)(ww + t * 64);
#pragma unroll
        for (int k = 0; k < 16; k++) {
            float4 v = wr[k];
            s += v.x + v.y + v.z + v.w;
        }
        g_Sw[t] = s;
    }
}

// wy[b][oc][j*64+c] = sum_e R[c][e]*T[b][oc][e*1024+j] + beta[c]*Sw[oc] + wb[oc]
__global__ __launch_bounds__(256) void kB(const float* __restrict__ wbias,
                                          float* __restrict__ out) {
    __shared__ __align__(16) float As[64 * 72];
    __shared__ __align__(16) float Ds[64 * 68];
    __shared__ float sb[64];
    const int oc = blockIdx.x, b = blockIdx.y, bz = blockIdx.z, t = threadIdx.x;
    const int w = t >> 5, lane = t & 31, gid = lane >> 2, tig = lane & 3;
    const int cs = w & 3, jh = w >> 2;
    if (t < 64) sb[t] = g_beta[b * 64 + t];
    const float swv = g_Sw[oc], wbv = wbias[oc];
    unsigned ar[8][4];
    const float* Rb = g_R + b * 4096;
#pragma unroll
    for (int k = 0; k < 8; k++) {
        int r = cs * 16 + gid, c = 8 * k + tig;
        ar[k][0] = f2tf(Rb[r * 64 + c]);
        ar[k][1] = f2tf(Rb[(r + 8) * 64 + c]);
        ar[k][2] = f2tf(Rb[r * 64 + c + 4]);
        ar[k][3] = f2tf(Rb[(r + 8) * 64 + c + 4]);
    }
    const float* Tb = g_T + ((long)(b * 64 + oc)) * 65536;
    float* ob = out + ((long)(b * 64 + oc)) * 65536;
    float ls = 0.f, lq = 0.f;
    const int e = t >> 2, q4 = t & 3;
    __syncthreads();
    for (int jt = bz * 4; jt < bz * 4 + 4; jt++) {
        int j0 = jt * 64;
#pragma unroll
        for (int kk = 0; kk < 4; kk++)
            *(float4*)(As + e * 72 + q4 * 16 + 4 * kk) =
                *(const float4*)(Tb + e * 1024 + j0 + q4 * 16 + 4 * kk);
        __syncthreads();
#pragma unroll
        for (int nt = 0; nt < 4; nt++) {
            float acc[4] = {0.f, 0.f, 0.f, 0.f};
            int jb = jh * 32 + nt * 8;
#pragma unroll
            for (int k = 0; k < 8; k++) {
                unsigned bh[2] = {f2tf(As[(8 * k + tig) * 72 + jb + gid]),
                                  f2tf(As[(8 * k + tig + 4) * 72 + jb + gid])};
                mma8(acc, ar[k], bh);
            }
            int c0 = cs * 16 + gid, jj = jb + 2 * tig;
            float bias0 = sb[c0] * swv + wbv, bias1 = sb[c0 + 8] * swv + wbv;
            Ds[jj * 68 + c0] = acc[0] + bias0;
            Ds[(jj + 1) * 68 + c0] = acc[1] + bias0;
            Ds[jj * 68 + c0 + 8] = acc[2] + bias1;
            Ds[(jj + 1) * 68 + c0 + 8] = acc[3] + bias1;
        }
        __syncthreads();
        {
            int j = t >> 2, h = t & 3;
#pragma unroll
            for (int kk = 0; kk < 4; kk++) {
                float4 v = *(const float4*)(Ds + j * 68 + h * 16 + 4 * kk);
                ls += v.x + v.y + v.z + v.w;
                lq += v.x * v.x + v.y * v.y + v.z * v.z + v.w * v.w;
                *(float4*)(ob + (j0 + j) * 64 + h * 16 + 4 * kk) = v;
            }
        }
        __syncthreads();
    }
#pragma unroll
    for (int o = 16; o >= 1; o >>= 1) {
        ls += __shfl_xor_sync(0xffffffffu, ls, o);
        lq += __shfl_xor_sync(0xffffffffu, lq, o);
    }
    if (lane == 0) { atomicAdd(&g_sum[oc], ls); atomicAdd(&g_sumsq[oc], lq); }
}

__global__ void k4(const float* __restrict__ gamma, const float* __restrict__ bnb) {
    int t = threadIdx.x;
    if (t < 64) {
        float m = g_sum[t] / CNT;
        float v = g_sumsq[t] / CNT - m * m;
        float sc = gamma[t] * rsqrtf(v + 1e-5f);
        g_scale[t] = sc;
        g_shift[t] = bnb[t] - m * sc;
    }
}

__global__ __launch_bounds__(256) void k5(const float* __restrict__ x, float* __restrict__ out) {
    long i4 = (long)blockIdx.x * 256 + threadIdx.x;
    int ch = (int)(i4 >> 14) & 63;
    float sc = __ldg(&g_scale[ch]), sh = __ldg(&g_shift[ch]);
    float4 wv = ((const float4*)out)[i4];
    float4 xv = ((const float4*)x)[i4];
    float4 o;
    o.x = wv.x * sc + sh + xv.x;
    o.y = wv.y * sc + sh + xv.y;
    o.z = wv.z * sc + sh + xv.z;
    o.w = wv.w * sc + sh + xv.w;
    ((float4*)out)[i4] = o;
}

extern "C" void kernel_launch(void* const* d_in, const int* in_sizes, int n_in,
                              void* d_out, int out_size) {
    const float* x  = (const float*)d_in[0];
    const float* tw = (const float*)d_in[1];
    const float* tb = (const float*)d_in[2];
    const float* pw = (const float*)d_in[3];
    const float* pb = (const float*)d_in[4];
    const float* gw = (const float*)d_in[5];
    const float* gb = (const float*)d_in[6];
    const float* ww = (const float*)d_in[7];
    const float* wb = (const float*)d_in[8];
    const float* gamma = (const float*)d_in[9];
    const float* bnb = (const float*)d_in[10];
    float* out = (float*)d_out;

    static cudaStream_t s2 = nullptr;
    static cudaEvent_t evA = nullptr, evB = nullptr;
    if (!s2) {
        cudaStreamCreateWithFlags(&s2, cudaStreamNonBlocking);
        cudaEventCreateWithFlags(&evA, cudaEventDisableTiming);
        cudaEventCreateWithFlags(&evB, cudaEventDisableTiming);
    }

    k0<<<64, 256>>>();
    // fork: kT (independent heavy producer of g_T) runs concurrently with kG+k2
    cudaEventRecord(evA, 0);
    cudaStreamWaitEvent(s2, evA, 0);
    kT<<<dim3(2, 256), 256, 0, s2>>>(x, ww);
    kG<<<dim3(128, 4), 256>>>(x);
    k2<<<4, 512>>>(tw, tb, pw, pb, gw, gb, ww);
    // join: kB needs g_T (s2) and g_R/g_beta/g_Sw (stream 0)
    cudaEventRecord(evB, s2);
    cudaStreamWaitEvent(0, evB, 0);
    kB<<<dim3(64, 4, 4), 256>>>(wb, out);
    k4<<<1, 64>>>(gamma, bnb);
    k5<<<16384, 256>>>(x, out);
}

// round 8
// speedup vs baseline: 2.2414x; 1.0395x over previous
#include <cuda_runtime.h>
#include <math.h>

#define CNT 262144.0f

__device__ float g_T[4L*64*65536];   // [b][oc][e*1024+j], stored as tf32 bit patterns
__device__ float g_Gx[4*64*64];
__device__ float g_Gq[4*64*64];
__device__ float g_sx[4*64];
__device__ float g_R[4*64*64];       // R[c][e]
__device__ float g_beta[4*64];
__device__ float g_Sw[64];
__device__ float g_sum[64], g_sumsq[64];

__device__ __forceinline__ unsigned f2tf(float f) {
    unsigned u; asm("cvt.rna.tf32.f32 %0, %1;" : "=r"(u) : "f"(f)); return u;
}
__device__ __forceinline__ void mma8(float* c, const unsigned* a, const unsigned* b) {
    asm("mma.sync.aligned.m16n8k8.row.col.f32.tf32.tf32.f32 "
        "{%0,%1,%2,%3},{%4,%5,%6,%7},{%8,%9},{%0,%1,%2,%3};"
        : "+f"(c[0]), "+f"(c[1]), "+f"(c[2]), "+f"(c[3])
        : "r"(a[0]), "r"(a[1]), "r"(a[2]), "r"(a[3]), "r"(b[0]), "r"(b[1]));
}

__global__ void k0() {
    int i = blockIdx.x * 256 + threadIdx.x;
    if (i < 16384) { g_Gx[i] = 0.f; g_Gq[i] = 0.f; }
    if (i < 256) g_sx[i] = 0.f;
    if (i < 64) { g_sum[i] = 0.f; g_sumsq[i] = 0.f; }
}

// Gram: Gx = Xhi Xhi^T, Gq = Xhi Xlo^T; plus column sums.
// Xhi/Xlo precomputed as tf32 bit patterns at load; inner loop is LDS+MMA only.
__global__ __launch_bounds__(256) void kG(const float* __restrict__ x) {
    extern __shared__ __align__(16) float dsm[];
    float* Xh = dsm;               // 64*132
    float* Xl = dsm + 64 * 132;    // 64*132
    const int b = blockIdx.y, t = threadIdx.x, w = t >> 5, lane = t & 31;
    const int gid = lane >> 2, tig = lane & 3;
    const int rs = w & 3, cg = w >> 2;
    const int cp = t >> 2, q = t & 3;
    float P[4][4], Q[4][4];
#pragma unroll
    for (int u = 0; u < 4; u++)
#pragma unroll
        for (int i = 0; i < 4; i++) { P[u][i] = 0.f; Q[u][i] = 0.f; }
    float sx = 0.f;
    for (int tt = 0; tt < 4; tt++) {
        int n0 = (blockIdx.x * 4 + tt) * 128;
        const float* src = x + ((long)(b * 64 + cp)) * 65536 + n0 + q * 32;
#pragma unroll
        for (int k = 0; k < 8; k++) {
            float4 v = *(const float4*)(src + 4 * k);
            sx += v.x + v.y + v.z + v.w;
            unsigned hx = f2tf(v.x), hy = f2tf(v.y), hz = f2tf(v.z), hw = f2tf(v.w);
            float4 hv = make_float4(__uint_as_float(hx), __uint_as_float(hy),
                                    __uint_as_float(hz), __uint_as_float(hw));
            float4 lv = make_float4(
                __uint_as_float(f2tf(v.x - hv.x)), __uint_as_float(f2tf(v.y - hv.y)),
                __uint_as_float(f2tf(v.z - hv.z)), __uint_as_float(f2tf(v.w - hv.w)));
            *(float4*)(Xh + cp * 132 + q * 32 + 4 * k) = hv;
            *(float4*)(Xl + cp * 132 + q * 32 + 4 * k) = lv;
        }
        __syncthreads();
        for (int ks = 0; ks < 16; ks++) {
            const int col = 8 * ks + tig, e0 = rs * 16 + gid;
            unsigned ah[4];
            ah[0] = __float_as_uint(Xh[e0 * 132 + col]);
            ah[1] = __float_as_uint(Xh[(e0 + 8) * 132 + col]);
            ah[2] = __float_as_uint(Xh[e0 * 132 + col + 4]);
            ah[3] = __float_as_uint(Xh[(e0 + 8) * 132 + col + 4]);
#pragma unroll
            for (int u = 0; u < 4; u++) {
                int ep = cg * 32 + 8 * u + gid;
                unsigned bh[2] = {__float_as_uint(Xh[ep * 132 + col]),
                                  __float_as_uint(Xh[ep * 132 + col + 4])};
                unsigned bl[2] = {__float_as_uint(Xl[ep * 132 + col]),
                                  __float_as_uint(Xl[ep * 132 + col + 4])};
                mma8(P[u], ah, bh);
                mma8(Q[u], ah, bl);
            }
        }
        __syncthreads();
    }
    float* Gp = g_Gx + b * 4096;
    float* Gq = g_Gq + b * 4096;
#pragma unroll
    for (int u = 0; u < 4; u++) {
        int r0 = rs * 16 + gid, c0 = cg * 32 + 8 * u + 2 * tig;
        atomicAdd(&Gp[r0 * 64 + c0], P[u][0]);
        atomicAdd(&Gp[r0 * 64 + c0 + 1], P[u][1]);
        atomicAdd(&Gp[(r0 + 8) * 64 + c0], P[u][2]);
        atomicAdd(&Gp[(r0 + 8) * 64 + c0 + 1], P[u][3]);
        atomicAdd(&Gq[r0 * 64 + c0], Q[u][0]);
        atomicAdd(&Gq[r0 * 64 + c0 + 1], Q[u][1]);
        atomicAdd(&Gq[(r0 + 8) * 64 + c0], Q[u][2]);
        atomicAdd(&Gq[(r0 + 8) * 64 + c0 + 1], Q[u][3]);
    }
    sx += __shfl_down_sync(0xffffffffu, sx, 1);
    sx += __shfl_down_sync(0xffffffffu, sx, 2);
    if (q == 0) atomicAdd(&g_sx[b * 64 + cp], sx);
}

// T[b][oc][e*1024+j] = sum_ch Wc[oc][ch] * x[b][e][ch*1024+j]; stored pre-tf32.
__global__ __launch_bounds__(256) void kT(const float* __restrict__ x,
                                          const float* __restrict__ ww) {
    __shared__ __align__(16) float Xs[64 * 132];
    const int be = blockIdx.y;
    const int b = be >> 6, e = be & 63;
    const int t = threadIdx.x, w = t >> 5, lane = t & 31;
    const int gid = lane >> 2, tig = lane & 3;
    const int rs = w & 3, jh = w >> 2;
    const int ch_ld = t >> 2, q = t & 3;
    unsigned aw[8][4];
#pragma unroll
    for (int k = 0; k < 8; k++) {
        int r = rs * 16 + gid, c = 8 * k + tig;
        aw[k][0] = f2tf(ww[r * 64 + c]);
        aw[k][1] = f2tf(ww[(r + 8) * 64 + c]);
        aw[k][2] = f2tf(ww[r * 64 + c + 4]);
        aw[k][3] = f2tf(ww[(r + 8) * 64 + c + 4]);
    }
    const float* xe = x + (long)be * 65536;
    for (int tt = 0; tt < 4; tt++) {
        int j0 = blockIdx.x * 512 + tt * 128;
        const float* src = xe + ch_ld * 1024 + j0 + q * 32;
#pragma unroll
        for (int k = 0; k < 8; k++)
            *(float4*)(Xs + ch_ld * 132 + q * 32 + 4 * k) = *(const float4*)(src + 4 * k);
        __syncthreads();
#pragma unroll
        for (int half = 0; half < 2; half++) {
            float acc[4][4];
#pragma unroll
            for (int u = 0; u < 4; u++)
#pragma unroll
                for (int i = 0; i < 4; i++) acc[u][i] = 0.f;
            int nb = jh * 64 + half * 32;
#pragma unroll
            for (int k = 0; k < 8; k++) {
#pragma unroll
                for (int u = 0; u < 4; u++) {
                    int nn = nb + 8 * u + gid;
                    unsigned bh[2] = {f2tf(Xs[(8 * k + tig) * 132 + nn]),
                                      f2tf(Xs[(8 * k + tig + 4) * 132 + nn])};
                    mma8(acc[u], aw[k], bh);
                }
            }
#pragma unroll
            for (int u = 0; u < 4; u++) {
                int oc = rs * 16 + gid, nn = nb + 8 * u + 2 * tig;
                float* d0 = g_T + ((long)(b * 64 + oc)) * 65536 + e * 1024 + j0 + nn;
                *(float2*)d0 = make_float2(__uint_as_float(f2tf(acc[u][0])),
                                           __uint_as_float(f2tf(acc[u][1])));
                *(float2*)(d0 + 8L * 65536) = make_float2(__uint_as_float(f2tf(acc[u][2])),
                                                          __uint_as_float(f2tf(acc[u][3])));
            }
        }
        __syncthreads();
    }
}

// f = Pw G Tw^T + rank1, softmax, R, beta, Sw  (G = Gx + Gq + Gq^T)
__global__ __launch_bounds__(512) void k2(
    const float* __restrict__ tw, const float* __restrict__ tb,
    const float* __restrict__ pw, const float* __restrict__ pb,
    const float* __restrict__ gw, const float* __restrict__ gb,
    const float* __restrict__ ww) {
    __shared__ float A[64 * 68], Bf[64 * 68];
    __shared__ float s_sx[64], s_tsx[64], s_psx[64], s_tb[64], s_pb[64], s_gb[64];
    const int b = blockIdx.x, t = threadIdx.x;
    const int ty = t >> 5, tx = t & 31;
    if (t < 64) { s_sx[t] = g_sx[b*64+t]; s_tb[t] = tb[t]; s_pb[t] = pb[t]; s_gb[t] = gb[t]; }
    for (int idx = t; idx < 4096; idx += 512) A[(idx & 63) * 68 + (idx >> 6)] = tw[idx];
    {
        const float* Gx = g_Gx + b * 4096;
        const float* Gq = g_Gq + b * 4096;
        for (int idx = t; idx < 4096; idx += 512) {
            int r = idx >> 6, c = idx & 63;
            Bf[r * 68 + c] = Gx[idx] + Gq[idx] + Gq[c * 64 + r];
        }
    }
    __syncthreads();
    if (t < 64) {
        float a1 = 0.f;
#pragma unroll 16
        for (int e = 0; e < 64; e++) a1 += A[e * 68 + t] * s_sx[e];
        s_tsx[t] = a1;
    }
    float acc[4][2];
#pragma unroll
    for (int i = 0; i < 4; i++) { acc[i][0] = 0.f; acc[i][1] = 0.f; }
#pragma unroll 8
    for (int e = 0; e < 64; e++) {
        float4 av = *(const float4*)(Bf + e * 68 + 4 * ty);
        float2 bv = *(const float2*)(A + e * 68 + 2 * tx);
        acc[0][0] += av.x*bv.x; acc[0][1] += av.x*bv.y;
        acc[1][0] += av.y*bv.x; acc[1][1] += av.y*bv.y;
        acc[2][0] += av.z*bv.x; acc[2][1] += av.z*bv.y;
        acc[3][0] += av.w*bv.x; acc[3][1] += av.w*bv.y;
    }
    __syncthreads();
#pragma unroll
    for (int i = 0; i < 4; i++) {
        Bf[(4*ty+i)*68 + 2*tx]     = acc[i][0];
        Bf[(4*ty+i)*68 + 2*tx + 1] = acc[i][1];
    }
    for (int idx = t; idx < 4096; idx += 512) A[(idx & 63) * 68 + (idx >> 6)] = pw[idx];
    __syncthreads();
    if (t < 64) {
        float a2 = 0.f;
#pragma unroll 16
        for (int e = 0; e < 64; e++) a2 += A[e * 68 + t] * s_sx[e];
        s_psx[t] = a2;
    }
#pragma unroll
    for (int i = 0; i < 4; i++) { acc[i][0] = 0.f; acc[i][1] = 0.f; }
#pragma unroll 8
    for (int e = 0; e < 64; e++) {
        float4 av = *(const float4*)(A + e*68 + 4*ty);
        float2 bv = *(const float2*)(Bf + e*68 + 2*tx);
        acc[0][0] += av.x*bv.x; acc[0][1] += av.x*bv.y;
        acc[1][0] += av.y*bv.x; acc[1][1] += av.y*bv.y;
        acc[2][0] += av.z*bv.x; acc[2][1] += av.z*bv.y;
        acc[3][0] += av.w*bv.x; acc[3][1] += av.w*bv.y;
    }
    __syncthreads();
#pragma unroll
    for (int i = 0; i < 4; i++)
#pragma unroll
        for (int j = 0; j < 2; j++) {
            int c = 4*ty+i, d = 2*tx+j;
            Bf[c*68+d] = acc[i][j] + s_pb[c]*(s_tsx[d] + 65536.f*s_tb[d]) + s_psx[c]*s_tb[d];
        }
    __syncthreads();
    {
        const int w = t >> 5, lane = t & 31;
        for (int c = w*4; c < w*4+4; c++) {
            float v0 = Bf[c*68+lane], v1 = Bf[c*68+32+lane];
            float m = fmaxf(v0, v1);
#pragma unroll
            for (int o = 16; o >= 1; o >>= 1) m = fmaxf(m, __shfl_xor_sync(0xffffffffu, m, o));
            float e0 = __expf(v0-m), e1 = __expf(v1-m), s = e0+e1;
#pragma unroll
            for (int o = 16; o >= 1; o >>= 1) s += __shfl_xor_sync(0xffffffffu, s, o);
            float inv = 1.f/s;
            A[lane*68+c] = e0*inv;
            A[(lane+32)*68+c] = e1*inv;
        }
    }
    __syncthreads();
    for (int idx = t; idx < 4096; idx += 512) Bf[(idx >> 6) * 68 + (idx & 63)] = gw[idx];
    __syncthreads();
    if (t < 64) {
        float bs = 0.f;
#pragma unroll 16
        for (int d = 0; d < 64; d++) bs += A[d*68+t]*s_gb[d];
        g_beta[b*64+t] = bs;
    }
#pragma unroll
    for (int i = 0; i < 4; i++) { acc[i][0] = 0.f; acc[i][1] = 0.f; }
#pragma unroll 8
    for (int d = 0; d < 64; d++) {
        float4 av = *(const float4*)(Bf + d*68 + 4*ty);
        float2 bv = *(const float2*)(A + d*68 + 2*tx);
        acc[0][0] += av.x*bv.x; acc[0][1] += av.x*bv.y;
        acc[1][0] += av.y*bv.x; acc[1][1] += av.y*bv.y;
        acc[2][0] += av.z*bv.x; acc[2][1] += av.z*bv.y;
        acc[3][0] += av.w*bv.x; acc[3][1] += av.w*bv.y;
    }
#pragma unroll
    for (int i = 0; i < 4; i++)
#pragma unroll
        for (int j = 0; j < 2; j++)
            g_R[b*4096 + (2*tx+j)*64 + (4*ty+i)] = acc[i][j];
    if (b == 0 && t < 64) {
        float s = 0.f;
        const float4* wr = (const float4*)(ww + t * 64);
#pragma unroll
        for (int k = 0; k < 16; k++) {
            float4 v = wr[k];
            s += v.x + v.y + v.z + v.w;
        }
        g_Sw[t] = s;
    }
}

// wy[b][oc][j*64+c] = sum_e R[c][e]*T[b][oc][e*1024+j] + beta[c]*Sw[oc] + wb[oc]
__global__ __launch_bounds__(256) void kB(const float* __restrict__ wbias,
                                          float* __restrict__ out) {
    __shared__ __align__(16) float As[64 * 72];
    __shared__ __align__(16) float Ds[64 * 68];
    __shared__ float sb[64];
    const int oc = blockIdx.x, b = blockIdx.y, bz = blockIdx.z, t = threadIdx.x;
    const int w = t >> 5, lane = t & 31, gid = lane >> 2, tig = lane & 3;
    const int cs = w & 3, jh = w >> 2;
    if (t < 64) sb[t] = g_beta[b * 64 + t];
    const float swv = g_Sw[oc], wbv = wbias[oc];
    unsigned ar[8][4];
    const float* Rb = g_R + b * 4096;
#pragma unroll
    for (int k = 0; k < 8; k++) {
        int r = cs * 16 + gid, c = 8 * k + tig;
        ar[k][0] = f2tf(Rb[r * 64 + c]);
        ar[k][1] = f2tf(Rb[(r + 8) * 64 + c]);
        ar[k][2] = f2tf(Rb[r * 64 + c + 4]);
        ar[k][3] = f2tf(Rb[(r + 8) * 64 + c + 4]);
    }
    const float* Tb = g_T + ((long)(b * 64 + oc)) * 65536;
    float* ob = out + ((long)(b * 64 + oc)) * 65536;
    float ls = 0.f, lq = 0.f;
    const int e = t >> 2, q4 = t & 3;
    __syncthreads();
    for (int jt = bz * 4; jt < bz * 4 + 4; jt++) {
        int j0 = jt * 64;
#pragma unroll
        for (int kk = 0; kk < 4; kk++)
            *(float4*)(As + e * 72 + q4 * 16 + 4 * kk) =
                *(const float4*)(Tb + e * 1024 + j0 + q4 * 16 + 4 * kk);
        __syncthreads();
#pragma unroll
        for (int nt = 0; nt < 4; nt++) {
            float acc[4] = {0.f, 0.f, 0.f, 0.f};
            int jb = jh * 32 + nt * 8;
#pragma unroll
            for (int k = 0; k < 8; k++) {
                unsigned bh[2] = {__float_as_uint(As[(8 * k + tig) * 72 + jb + gid]),
                                  __float_as_uint(As[(8 * k + tig + 4) * 72 + jb + gid])};
                mma8(acc, ar[k], bh);
            }
            int c0 = cs * 16 + gid, jj = jb + 2 * tig;
            float bias0 = sb[c0] * swv + wbv, bias1 = sb[c0 + 8] * swv + wbv;
            Ds[jj * 68 + c0] = acc[0] + bias0;
            Ds[(jj + 1) * 68 + c0] = acc[1] + bias0;
            Ds[jj * 68 + c0 + 8] = acc[2] + bias1;
            Ds[(jj + 1) * 68 + c0 + 8] = acc[3] + bias1;
        }
        __syncthreads();
        {
            int j = t >> 2, h = t & 3;
#pragma unroll
            for (int kk = 0; kk < 4; kk++) {
                float4 v = *(const float4*)(Ds + j * 68 + h * 16 + 4 * kk);
                ls += v.x + v.y + v.z + v.w;
                lq += v.x * v.x + v.y * v.y + v.z * v.z + v.w * v.w;
                *(float4*)(ob + (j0 + j) * 64 + h * 16 + 4 * kk) = v;
            }
        }
        __syncthreads();
    }
#pragma unroll
    for (int o = 16; o >= 1; o >>= 1) {
        ls += __shfl_xor_sync(0xffffffffu, ls, o);
        lq += __shfl_xor_sync(0xffffffffu, lq, o);
    }
    if (lane == 0) { atomicAdd(&g_sum[oc], ls); atomicAdd(&g_sumsq[oc], lq); }
}

// BN apply + residual; scale/shift computed inline (k4 eliminated).
__global__ __launch_bounds__(256) void k5(const float* __restrict__ x,
                                          const float* __restrict__ gamma,
                                          const float* __restrict__ bnb,
                                          float* __restrict__ out) {
    long i4 = (long)blockIdx.x * 256 + threadIdx.x;
    int ch = (int)(i4 >> 14) & 63;
    float m = __ldg(&g_sum[ch]) * (1.f / CNT);
    float v = __ldg(&g_sumsq[ch]) * (1.f / CNT) - m * m;
    float sc = __ldg(&gamma[ch]) * rsqrtf(v + 1e-5f);
    float sh = __ldg(&bnb[ch]) - m * sc;
    float4 wv = ((const float4*)out)[i4];
    float4 xv = ((const float4*)x)[i4];
    float4 o;
    o.x = wv.x * sc + sh + xv.x;
    o.y = wv.y * sc + sh + xv.y;
    o.z = wv.z * sc + sh + xv.z;
    o.w = wv.w * sc + sh + xv.w;
    ((float4*)out)[i4] = o;
}

extern "C" void kernel_launch(void* const* d_in, const int* in_sizes, int n_in,
                              void* d_out, int out_size) {
    const float* x  = (const float*)d_in[0];
    const float* tw = (const float*)d_in[1];
    const float* tb = (const float*)d_in[2];
    const float* pw = (const float*)d_in[3];
    const float* pb = (const float*)d_in[4];
    const float* gw = (const float*)d_in[5];
    const float* gb = (const float*)d_in[6];
    const float* ww = (const float*)d_in[7];
    const float* wb = (const float*)d_in[8];
    const float* gamma = (const float*)d_in[9];
    const float* bnb = (const float*)d_in[10];
    float* out = (float*)d_out;

    static cudaStream_t s2 = nullptr;
    static cudaEvent_t evA = nullptr, evB = nullptr;
    if (!s2) {
        cudaStreamCreateWithFlags(&s2, cudaStreamNonBlocking);
        cudaEventCreateWithFlags(&evA, cudaEventDisableTiming);
        cudaEventCreateWithFlags(&evB, cudaEventDisableTiming);
        cudaFuncSetAttribute(kG, cudaFuncAttributeMaxDynamicSharedMemorySize, 70000);
    }
    const int kg_smem = 2 * 64 * 132 * 4;

    k0<<<64, 256>>>();
    cudaEventRecord(evA, 0);
    cudaStreamWaitEvent(s2, evA, 0);
    kT<<<dim3(2, 256), 256, 0, s2>>>(x, ww);
    kG<<<dim3(128, 4), 256, kg_smem>>>(x);
    k2<<<4, 512>>>(tw, tb, pw, pb, gw, gb, ww);
    cudaEventRecord(evB, s2);
    cudaStreamWaitEvent(0, evB, 0);
    kB<<<dim3(64, 4, 4), 256>>>(wb, out);
    k5<<<16384, 256>>>(x, gamma, bnb, out);
}